// round 14
// baseline (speedup 1.0000x reference)
#include <cuda_runtime.h>
#include <cuda_fp16.h>
#include <math.h>
#include <stdint.h>

#define L 16384
#define D 1024
#define ADIM 1024

#define BM 128
#define BN 128
#define BK 64
#define NCH (D / BK)               // 16
#define STAGES 3

#define TILEB (BM * BK * 2)        // 16384 B per 128x64 fp16 tile
#define OFF_A  0
#define OFF_BH (TILEB)
#define OFF_BL (2 * TILEB)
#define STAGEB (3 * TILEB)         // 49152
#define SMEM_TOTAL (STAGES * STAGEB) // 147456

// ---------------------------------------------------------------------------
// Device scratch
// ---------------------------------------------------------------------------
__device__ __half g_A[(size_t)L * D];      // h_i (single fp16)
__device__ __half g_hB[(size_t)ADIM * D];  // W1 hi (fp16)
__device__ __half g_lB[(size_t)ADIM * D];  // W1 lo (fp16 residual)
__device__ float g_c[ADIM];
__device__ float g_beta[L];
__device__ unsigned g_maxbits;
__device__ float g_sumexp;

// ---------------------------------------------------------------------------
// helpers
// ---------------------------------------------------------------------------
__device__ __forceinline__ uint32_t smem_u32(const void* p) {
    uint32_t a;
    asm("{ .reg .u64 t; cvta.to.shared.u64 t, %1; cvt.u32.u64 %0, t; }" : "=r"(a) : "l"(p));
    return a;
}
__device__ __forceinline__ void cpa16(uint32_t dst, const void* src) {
    asm volatile("cp.async.cg.shared.global [%0], [%1], 16;" :: "r"(dst), "l"(src));
}
__device__ __forceinline__ void cpa_commit() {
    asm volatile("cp.async.commit_group;");
}
__device__ __forceinline__ void cpa_wait1() {
    asm volatile("cp.async.wait_group 1;" ::: "memory");
}
__device__ __forceinline__ void cpa_wait0() {
    asm volatile("cp.async.wait_group 0;" ::: "memory");
}
__device__ __forceinline__ void ldm4(uint32_t* r, uint32_t addr) {
    asm volatile("ldmatrix.sync.aligned.m8n8.x4.shared.b16 {%0,%1,%2,%3}, [%4];"
                 : "=r"(r[0]), "=r"(r[1]), "=r"(r[2]), "=r"(r[3]) : "r"(addr));
}
__device__ __forceinline__ void mma16816(float* d, const uint32_t* a, uint32_t b0, uint32_t b1) {
    asm volatile("mma.sync.aligned.m16n8k16.row.col.f32.f16.f16.f32 "
                 "{%0,%1,%2,%3}, {%4,%5,%6,%7}, {%8,%9}, {%0,%1,%2,%3};"
                 : "+f"(d[0]), "+f"(d[1]), "+f"(d[2]), "+f"(d[3])
                 : "r"(a[0]), "r"(a[1]), "r"(a[2]), "r"(a[3]), "r"(b0), "r"(b1));
}
__device__ __forceinline__ float tanh_fast(float x) {
    float e, r;
    asm("ex2.approx.f32 %0, %1;" : "=f"(e) : "f"(x * 2.88539008177792681f));
    asm("rcp.approx.f32 %0, %1;" : "=f"(r) : "f"(e + 1.0f));
    return fmaf(-2.0f, r, 1.0f);
}
__device__ __forceinline__ unsigned enc_f(float f) {
    unsigned u = __float_as_uint(f);
    return (u & 0x80000000u) ? ~u : (u | 0x80000000u);
}
__device__ __forceinline__ float dec_f(unsigned e) {
    unsigned u = (e & 0x80000000u) ? (e ^ 0x80000000u) : ~e;
    return __uint_as_float(u);
}
__device__ __forceinline__ void split8h(const float* src, uint4* hi, uint4* lo) {
    float4 v0 = *(const float4*)src;
    float4 v1 = *(const float4*)(src + 4);
    float vs[8] = {v0.x, v0.y, v0.z, v0.w, v1.x, v1.y, v1.z, v1.w};
    unsigned short hs[8], ls[8];
    #pragma unroll
    for (int k = 0; k < 8; k++) {
        __half h = __float2half_rn(vs[k]);
        hs[k] = __half_as_ushort(h);
        ls[k] = __half_as_ushort(__float2half_rn(vs[k] - __half2float(h)));
    }
    *hi = *(uint4*)hs;
    *lo = *(uint4*)ls;
}

// ---------------------------------------------------------------------------
// K1: c[a] = dot(W_att[a, D:2D], h_t) + b_att[a]  (+ folded init)
// ---------------------------------------------------------------------------
__global__ void k_ctx(const float* __restrict__ W, const float* __restrict__ ht,
                      const float* __restrict__ b, float* __restrict__ out) {
    int a = blockIdx.x;
    if (threadIdx.x < 16) g_beta[a * 16 + threadIdx.x] = 0.0f;
    if (a < 4) out[a * 256 + threadIdx.x] = 0.0f;
    if (a == 0 && threadIdx.x == 0) { g_maxbits = 0u; g_sumexp = 0.0f; }

    const float* w = W + (size_t)a * (2 * D) + D;
    // vectorized: 256 threads x 1 float4 = 1024 floats
    float4 wv = ((const float4*)w)[threadIdx.x];
    float4 hv = ((const float4*)ht)[threadIdx.x];
    float s = wv.x * hv.x + wv.y * hv.y + wv.z * hv.z + wv.w * hv.w;
    __shared__ float red[8];
    #pragma unroll
    for (int o = 16; o > 0; o >>= 1) s += __shfl_down_sync(0xffffffffu, s, o);
    if ((threadIdx.x & 31) == 0) red[threadIdx.x >> 5] = s;
    __syncthreads();
    if (threadIdx.x == 0) {
        float t = 0.0f;
        #pragma unroll
        for (int i = 0; i < 8; i++) t += red[i];
        g_c[a] = t + b[a];
    }
}

// ---------------------------------------------------------------------------
// K2a: h_i -> single fp16; 16 floats/thread, loads front-batched (MLP 4)
// ---------------------------------------------------------------------------
__global__ void __launch_bounds__(256) k_conv_h(const float* __restrict__ h) {
    size_t i = ((size_t)blockIdx.x * 256 + threadIdx.x) * 16;
    float4 v0 = *(const float4*)(h + i);
    float4 v1 = *(const float4*)(h + i + 4);
    float4 v2 = *(const float4*)(h + i + 8);
    float4 v3 = *(const float4*)(h + i + 12);
    float vs[16] = {v0.x, v0.y, v0.z, v0.w, v1.x, v1.y, v1.z, v1.w,
                    v2.x, v2.y, v2.z, v2.w, v3.x, v3.y, v3.z, v3.w};
    unsigned short hs[16];
    #pragma unroll
    for (int k = 0; k < 16; k++) hs[k] = __half_as_ushort(__float2half_rn(vs[k]));
    *(uint4*)(g_A + i) = *(uint4*)hs;
    *(uint4*)(g_A + i + 8) = *(uint4*)(hs + 8);
}

// ---------------------------------------------------------------------------
// K2b: W1 -> (hi, lo) fp16; 8 floats/thread
// ---------------------------------------------------------------------------
__global__ void __launch_bounds__(256) k_conv_w(const float* __restrict__ W) {
    int q = blockIdx.x * 256 + threadIdx.x;
    int a = q >> 7, c = (q & 127) * 8;
    const float* src = W + (size_t)a * (2 * D) + c;
    size_t o = (size_t)a * D + c;
    uint4 hv, lv;
    split8h(src, &hv, &lv);
    *(uint4*)(g_hB + o) = hv;
    *(uint4*)(g_lB + o) = lv;
}

// ---------------------------------------------------------------------------
// K3: fp16 HMMA GEMM — 2 passes (A single, B double), BK=64, 3-stage
// ---------------------------------------------------------------------------
__global__ void __launch_bounds__(256, 1) k_gemm(const float* __restrict__ u_in) {
    extern __shared__ __align__(128) char smem[];
    const uint32_t sbase = smem_u32(smem);
    const int tid = threadIdx.x;
    const int lane = tid & 31, wid = tid >> 5;
    const int warp_m = wid >> 2, warp_n = wid & 3;
    const int a0 = blockIdx.x * BN;       // a-tile fast
    const int l0 = blockIdx.y * BM;

    const int crow = tid >> 3;
    const int cch = tid & 7;
    const uint32_t swz_ch = (uint32_t)(cch ^ (crow & 7));
    const uint32_t dbase = (uint32_t)crow * 128 + swz_ch * 16;
    const char* pA  = (const char*)(g_A  + ((size_t)(l0 + crow) * D + cch * 8));
    const char* pBh = (const char*)(g_hB + ((size_t)(a0 + crow) * D + cch * 8));
    const char* pBl = (const char*)(g_lB + ((size_t)(a0 + crow) * D + cch * 8));
    const size_t gstep = (size_t)32 * D * 2;

    uint32_t aRow[4], aSw[4];
    #pragma unroll
    for (int i = 0; i < 4; i++) {
        int r = warp_m * 64 + i * 16 + (lane & 15);
        aRow[i] = (uint32_t)r * 128;
        aSw[i] = (uint32_t)(r & 7);
    }
    const uint32_t aCh = (uint32_t)(lane >> 4);
    uint32_t bRow[2], bSw[2];
    #pragma unroll
    for (int p = 0; p < 2; p++) {
        int r = warp_n * 32 + p * 16 + (lane & 7) + ((lane >> 4) & 1) * 8;
        bRow[p] = (uint32_t)r * 128;
        bSw[p] = (uint32_t)(r & 7);
    }
    const uint32_t bCh = (uint32_t)((lane >> 3) & 1);

    float acc[4][4][4];
    #pragma unroll
    for (int i = 0; i < 4; i++)
        #pragma unroll
        for (int j = 0; j < 4; j++)
            #pragma unroll
            for (int r = 0; r < 4; r++) acc[i][j][r] = 0.0f;

    auto issue = [&](int kc, int st) {
        const uint32_t sb = sbase + (uint32_t)st * STAGEB;
        const size_t ko = (size_t)kc * BK * 2;
        #pragma unroll
        for (int i = 0; i < 4; i++) {
            const size_t go = ko + (size_t)i * gstep;
            const uint32_t doff = dbase + (uint32_t)i * 32 * 128;
            cpa16(sb + OFF_A  + doff, pA  + go);
            cpa16(sb + OFF_BH + doff, pBh + go);
            cpa16(sb + OFF_BL + doff, pBl + go);
        }
        cpa_commit();
    };

    issue(0, 0);
    issue(1, 1);

    for (int kc = 0; kc < NCH; kc++) {
        if (kc == NCH - 1) cpa_wait0(); else cpa_wait1();
        __syncthreads();
        if (kc + 2 < NCH) issue(kc + 2, (kc + 2) % STAGES);

        const uint32_t base = sbase + (uint32_t)(kc % STAGES) * STAGEB;
        #pragma unroll
        for (int ks = 0; ks < 4; ks++) {
            uint32_t af[4][4], bh[2][4], bl[2][4];
            const uint32_t ac = (uint32_t)ks * 2 + aCh;
            const uint32_t bc = (uint32_t)ks * 2 + bCh;
            #pragma unroll
            for (int i = 0; i < 4; i++) {
                uint32_t ad = base + aRow[i] + ((ac ^ aSw[i]) << 4);
                ldm4(af[i], ad + OFF_A);
            }
            #pragma unroll
            for (int p = 0; p < 2; p++) {
                uint32_t bd = base + bRow[p] + ((bc ^ bSw[p]) << 4);
                ldm4(bh[p], bd + OFF_BH);
                ldm4(bl[p], bd + OFF_BL);
            }
            #pragma unroll
            for (int i = 0; i < 4; i++)
                #pragma unroll
                for (int j = 0; j < 4; j++) {
                    const int p = j >> 1, q = (j & 1) * 2;
                    mma16816(acc[i][j], af[i], bh[p][q], bh[p][q + 1]);
                    mma16816(acc[i][j], af[i], bl[p][q], bl[p][q + 1]);
                }
        }
    }

    // ---- epilogue
    const int gID = lane >> 2, tig = lane & 3;
    float cl[4][2], ul[4][2];
    #pragma unroll
    for (int j = 0; j < 4; j++) {
        const int ag = a0 + warp_n * 32 + j * 8 + 2 * tig;
        cl[j][0] = g_c[ag];  cl[j][1] = g_c[ag + 1];
        ul[j][0] = u_in[ag]; ul[j][1] = u_in[ag + 1];
    }
    #pragma unroll
    for (int i = 0; i < 4; i++) {
        float sA = 0.0f, sB = 0.0f;
        #pragma unroll
        for (int j = 0; j < 4; j++) {
            sA = fmaf(tanh_fast(acc[i][j][0] + cl[j][0]), ul[j][0], sA);
            sA = fmaf(tanh_fast(acc[i][j][1] + cl[j][1]), ul[j][1], sA);
            sB = fmaf(tanh_fast(acc[i][j][2] + cl[j][0]), ul[j][0], sB);
            sB = fmaf(tanh_fast(acc[i][j][3] + cl[j][1]), ul[j][1], sB);
        }
        sA += __shfl_xor_sync(0xffffffffu, sA, 1);
        sA += __shfl_xor_sync(0xffffffffu, sA, 2);
        sB += __shfl_xor_sync(0xffffffffu, sB, 1);
        sB += __shfl_xor_sync(0xffffffffu, sB, 2);
        if (tig == 0) {
            const int r = l0 + warp_m * 64 + i * 16 + gID;
            atomicAdd(&g_beta[r], sA);
            atomicAdd(&g_beta[r + 8], sB);
        }
    }
}

// ---------------------------------------------------------------------------
// K4: global max of beta
// ---------------------------------------------------------------------------
__global__ void k_max() {
    int i = blockIdx.x * 1024 + threadIdx.x;
    float v = g_beta[i];
    #pragma unroll
    for (int o = 16; o > 0; o >>= 1) v = fmaxf(v, __shfl_xor_sync(0xffffffffu, v, o));
    __shared__ float r[32];
    if ((threadIdx.x & 31) == 0) r[threadIdx.x >> 5] = v;
    __syncthreads();
    if (threadIdx.x < 32) {
        v = r[threadIdx.x];
        #pragma unroll
        for (int o = 16; o > 0; o >>= 1) v = fmaxf(v, __shfl_xor_sync(0xffffffffu, v, o));
        if (threadIdx.x == 0) atomicMax(&g_maxbits, enc_f(v));
    }
}

// ---------------------------------------------------------------------------
// K5: unnormalized s[d] += sum_l exp(beta_l - max) * h_i[l][d]; also sumexp
//   rows unrolled x2 for 8 outstanding loads
// ---------------------------------------------------------------------------
#define OROWS 128
__global__ void __launch_bounds__(256) k_out(const float* __restrict__ h_i,
                                             float* __restrict__ out) {
    __shared__ float w[OROWS];
    int l0 = blockIdx.x * OROWS;
    int tid = threadIdx.x;
    float mx = dec_f(g_maxbits);
    if (tid < OROWS) w[tid] = expf(g_beta[l0 + tid] - mx);
    __syncthreads();
    if (tid < 32) {
        float s = 0.0f;
        #pragma unroll
        for (int k = 0; k < OROWS / 32; k++) s += w[tid + k * 32];
        #pragma unroll
        for (int o = 16; o > 0; o >>= 1) s += __shfl_xor_sync(0xffffffffu, s, o);
        if (tid == 0) atomicAdd(&g_sumexp, s);
    }
    float acc[4] = {0.0f, 0.0f, 0.0f, 0.0f};
    #pragma unroll 1
    for (int l = 0; l < OROWS; l += 2) {
        float w0 = w[l], w1 = w[l + 1];
        const float* r0 = h_i + (size_t)(l0 + l) * D;
        const float* r1 = r0 + D;
        float v0[4], v1[4];
        #pragma unroll
        for (int j = 0; j < 4; j++) v0[j] = r0[tid + j * 256];
        #pragma unroll
        for (int j = 0; j < 4; j++) v1[j] = r1[tid + j * 256];
        #pragma unroll
        for (int j = 0; j < 4; j++)
            acc[j] = fmaf(w1, v1[j], fmaf(w0, v0[j], acc[j]));
    }
    #pragma unroll
    for (int j = 0; j < 4; j++) atomicAdd(&out[tid + j * 256], acc[j]);
}

// ---------------------------------------------------------------------------
// K6: normalize out by 1/sumexp
// ---------------------------------------------------------------------------
__global__ void k_norm(float* __restrict__ out) {
    float inv = __frcp_rn(g_sumexp);
    out[blockIdx.x * 256 + threadIdx.x] *= inv;
}

// ---------------------------------------------------------------------------
extern "C" void kernel_launch(void* const* d_in, const int* in_sizes, int n_in,
                              void* d_out, int out_size) {
    const float* h_i = (const float*)d_in[0];
    const float* h_t = (const float*)d_in[1];
    const float* W   = (const float*)d_in[2];
    const float* b   = (const float*)d_in[3];
    const float* u   = (const float*)d_in[4];
    float* out = (float*)d_out;

    static bool attr_set = false;
    if (!attr_set) {
        cudaFuncSetAttribute(k_gemm, cudaFuncAttributeMaxDynamicSharedMemorySize, SMEM_TOTAL);
        attr_set = true;
    }

    // k_gemm stays 4th so the ncu window keeps landing on it
    k_ctx<<<ADIM, 256>>>(W, h_t, b, out);
    k_conv_h<<<(int)(((size_t)L * D) / 4096), 256>>>(h_i);
    k_conv_w<<<(ADIM * D / 8) / 256, 256>>>(W);
    dim3 g(ADIM / BN, L / BM);
    k_gemm<<<g, 256, SMEM_TOTAL>>>(u);
    k_max<<<16, 1024>>>();
    k_out<<<L / OROWS, 256>>>(h_i, out);
    k_norm<<<4, 256>>>(out);
}

// round 15
// speedup vs baseline: 1.1123x; 1.1123x over previous
#include <cuda_runtime.h>
#include <cuda_fp16.h>
#include <math.h>
#include <stdint.h>

#define L 16384
#define D 1024
#define ADIM 1024

#define BM 128
#define BN 128
#define BK 64
#define NCH (D / BK)               // 16
#define STAGES 3

#define TILEB (BM * BK * 2)        // 16384 B per 128x64 fp16 tile
#define OFF_A  0
#define OFF_BH (TILEB)
#define OFF_BL (2 * TILEB)
#define STAGEB (3 * TILEB)         // 49152
#define SMEM_TOTAL (STAGES * STAGEB) // 147456

// ---------------------------------------------------------------------------
// Device scratch
// ---------------------------------------------------------------------------
__device__ __half g_A[(size_t)L * D];      // h_i (single fp16)
__device__ __half g_hB[(size_t)ADIM * D];  // W1 hi (fp16)
__device__ __half g_lB[(size_t)ADIM * D];  // W1 lo (fp16 residual)
__device__ float g_c[ADIM];
__device__ float g_beta[L];
__device__ unsigned g_maxbits;
__device__ float g_sumexp;

// ---------------------------------------------------------------------------
// helpers
// ---------------------------------------------------------------------------
__device__ __forceinline__ uint32_t smem_u32(const void* p) {
    uint32_t a;
    asm("{ .reg .u64 t; cvta.to.shared.u64 t, %1; cvt.u32.u64 %0, t; }" : "=r"(a) : "l"(p));
    return a;
}
__device__ __forceinline__ void cpa16(uint32_t dst, const void* src) {
    asm volatile("cp.async.cg.shared.global [%0], [%1], 16;" :: "r"(dst), "l"(src));
}
__device__ __forceinline__ void cpa_commit() {
    asm volatile("cp.async.commit_group;");
}
__device__ __forceinline__ void cpa_wait1() {
    asm volatile("cp.async.wait_group 1;" ::: "memory");
}
__device__ __forceinline__ void cpa_wait0() {
    asm volatile("cp.async.wait_group 0;" ::: "memory");
}
__device__ __forceinline__ void ldm4(uint32_t* r, uint32_t addr) {
    asm volatile("ldmatrix.sync.aligned.m8n8.x4.shared.b16 {%0,%1,%2,%3}, [%4];"
                 : "=r"(r[0]), "=r"(r[1]), "=r"(r[2]), "=r"(r[3]) : "r"(addr));
}
__device__ __forceinline__ void mma16816(float* d, const uint32_t* a, uint32_t b0, uint32_t b1) {
    asm volatile("mma.sync.aligned.m16n8k16.row.col.f32.f16.f16.f32 "
                 "{%0,%1,%2,%3}, {%4,%5,%6,%7}, {%8,%9}, {%0,%1,%2,%3};"
                 : "+f"(d[0]), "+f"(d[1]), "+f"(d[2]), "+f"(d[3])
                 : "r"(a[0]), "r"(a[1]), "r"(a[2]), "r"(a[3]), "r"(b0), "r"(b1));
}
__device__ __forceinline__ float tanh_fast(float x) {
    float e, r;
    asm("ex2.approx.f32 %0, %1;" : "=f"(e) : "f"(x * 2.88539008177792681f));
    asm("rcp.approx.f32 %0, %1;" : "=f"(r) : "f"(e + 1.0f));
    return fmaf(-2.0f, r, 1.0f);
}
__device__ __forceinline__ unsigned enc_f(float f) {
    unsigned u = __float_as_uint(f);
    return (u & 0x80000000u) ? ~u : (u | 0x80000000u);
}
__device__ __forceinline__ float dec_f(unsigned e) {
    unsigned u = (e & 0x80000000u) ? (e ^ 0x80000000u) : ~e;
    return __uint_as_float(u);
}
__device__ __forceinline__ void split8h(const float* src, uint4* hi, uint4* lo) {
    float4 v0 = *(const float4*)src;
    float4 v1 = *(const float4*)(src + 4);
    float vs[8] = {v0.x, v0.y, v0.z, v0.w, v1.x, v1.y, v1.z, v1.w};
    unsigned short hs[8], ls[8];
    #pragma unroll
    for (int k = 0; k < 8; k++) {
        __half h = __float2half_rn(vs[k]);
        hs[k] = __half_as_ushort(h);
        ls[k] = __half_as_ushort(__float2half_rn(vs[k] - __half2float(h)));
    }
    *hi = *(uint4*)hs;
    *lo = *(uint4*)ls;
}
__device__ __forceinline__ void cvt8h(const float* src, uint4* hi) {
    float4 v0 = *(const float4*)src;
    float4 v1 = *(const float4*)(src + 4);
    float vs[8] = {v0.x, v0.y, v0.z, v0.w, v1.x, v1.y, v1.z, v1.w};
    unsigned short hs[8];
    #pragma unroll
    for (int k = 0; k < 8; k++) hs[k] = __half_as_ushort(__float2half_rn(vs[k]));
    *hi = *(uint4*)hs;
}

// ---------------------------------------------------------------------------
// K1: c[a] = dot(W_att[a, D:2D], h_t) + b_att[a]  (+ folded init)
// ---------------------------------------------------------------------------
__global__ void k_ctx(const float* __restrict__ W, const float* __restrict__ ht,
                      const float* __restrict__ b, float* __restrict__ out) {
    int a = blockIdx.x;
    if (threadIdx.x < 16) g_beta[a * 16 + threadIdx.x] = 0.0f;
    if (a < 4) out[a * 256 + threadIdx.x] = 0.0f;
    if (a == 0 && threadIdx.x == 0) { g_maxbits = 0u; g_sumexp = 0.0f; }

    const float* w = W + (size_t)a * (2 * D) + D;
    float4 wv = ((const float4*)w)[threadIdx.x];
    float4 hv = ((const float4*)ht)[threadIdx.x];
    float s = wv.x * hv.x + wv.y * hv.y + wv.z * hv.z + wv.w * hv.w;
    __shared__ float red[8];
    #pragma unroll
    for (int o = 16; o > 0; o >>= 1) s += __shfl_down_sync(0xffffffffu, s, o);
    if ((threadIdx.x & 31) == 0) red[threadIdx.x >> 5] = s;
    __syncthreads();
    if (threadIdx.x == 0) {
        float t = 0.0f;
        #pragma unroll
        for (int i = 0; i < 8; i++) t += red[i];
        g_c[a] = t + b[a];
    }
}

// ---------------------------------------------------------------------------
// K2: fused conversion — blocks [0, HBLK): h_i -> fp16 (8 floats/thread);
//                        blocks [HBLK, HBLK+WBLK): W1 -> (hi,lo) fp16
// ---------------------------------------------------------------------------
#define HBLK 8192   // (L*D)/(256*8)
#define WBLK 512    // (A*D)/(256*8)
__global__ void __launch_bounds__(256) k_conv(const float* __restrict__ h,
                                              const float* __restrict__ W) {
    if (blockIdx.x < HBLK) {
        size_t i = ((size_t)blockIdx.x * 256 + threadIdx.x) * 8;
        uint4 hv;
        cvt8h(h + i, &hv);
        *(uint4*)(g_A + i) = hv;
    } else {
        int q = (blockIdx.x - HBLK) * 256 + threadIdx.x;
        int a = q >> 7, c = (q & 127) * 8;
        const float* src = W + (size_t)a * (2 * D) + c;
        size_t o = (size_t)a * D + c;
        uint4 hv, lv;
        split8h(src, &hv, &lv);
        *(uint4*)(g_hB + o) = hv;
        *(uint4*)(g_lB + o) = lv;
    }
}

// ---------------------------------------------------------------------------
// K3: fp16 HMMA GEMM — 2 passes (A single, B double), BK=64, 3-stage
// ---------------------------------------------------------------------------
__global__ void __launch_bounds__(256, 1) k_gemm(const float* __restrict__ u_in) {
    extern __shared__ __align__(128) char smem[];
    const uint32_t sbase = smem_u32(smem);
    const int tid = threadIdx.x;
    const int lane = tid & 31, wid = tid >> 5;
    const int warp_m = wid >> 2, warp_n = wid & 3;
    const int a0 = blockIdx.x * BN;       // a-tile fast
    const int l0 = blockIdx.y * BM;

    const int crow = tid >> 3;
    const int cch = tid & 7;
    const uint32_t swz_ch = (uint32_t)(cch ^ (crow & 7));
    const uint32_t dbase = (uint32_t)crow * 128 + swz_ch * 16;
    const char* pA  = (const char*)(g_A  + ((size_t)(l0 + crow) * D + cch * 8));
    const char* pBh = (const char*)(g_hB + ((size_t)(a0 + crow) * D + cch * 8));
    const char* pBl = (const char*)(g_lB + ((size_t)(a0 + crow) * D + cch * 8));
    const size_t gstep = (size_t)32 * D * 2;

    uint32_t aRow[4], aSw[4];
    #pragma unroll
    for (int i = 0; i < 4; i++) {
        int r = warp_m * 64 + i * 16 + (lane & 15);
        aRow[i] = (uint32_t)r * 128;
        aSw[i] = (uint32_t)(r & 7);
    }
    const uint32_t aCh = (uint32_t)(lane >> 4);
    uint32_t bRow[2], bSw[2];
    #pragma unroll
    for (int p = 0; p < 2; p++) {
        int r = warp_n * 32 + p * 16 + (lane & 7) + ((lane >> 4) & 1) * 8;
        bRow[p] = (uint32_t)r * 128;
        bSw[p] = (uint32_t)(r & 7);
    }
    const uint32_t bCh = (uint32_t)((lane >> 3) & 1);

    float acc[4][4][4];
    #pragma unroll
    for (int i = 0; i < 4; i++)
        #pragma unroll
        for (int j = 0; j < 4; j++)
            #pragma unroll
            for (int r = 0; r < 4; r++) acc[i][j][r] = 0.0f;

    auto issue = [&](int kc, int st) {
        const uint32_t sb = sbase + (uint32_t)st * STAGEB;
        const size_t ko = (size_t)kc * BK * 2;
        #pragma unroll
        for (int i = 0; i < 4; i++) {
            const size_t go = ko + (size_t)i * gstep;
            const uint32_t doff = dbase + (uint32_t)i * 32 * 128;
            cpa16(sb + OFF_A  + doff, pA  + go);
            cpa16(sb + OFF_BH + doff, pBh + go);
            cpa16(sb + OFF_BL + doff, pBl + go);
        }
        cpa_commit();
    };

    issue(0, 0);
    issue(1, 1);

    for (int kc = 0; kc < NCH; kc++) {
        if (kc == NCH - 1) cpa_wait0(); else cpa_wait1();
        __syncthreads();
        if (kc + 2 < NCH) issue(kc + 2, (kc + 2) % STAGES);

        const uint32_t base = sbase + (uint32_t)(kc % STAGES) * STAGEB;
        #pragma unroll
        for (int ks = 0; ks < 4; ks++) {
            uint32_t af[4][4], bh[2][4], bl[2][4];
            const uint32_t ac = (uint32_t)ks * 2 + aCh;
            const uint32_t bc = (uint32_t)ks * 2 + bCh;
            #pragma unroll
            for (int i = 0; i < 4; i++) {
                uint32_t ad = base + aRow[i] + ((ac ^ aSw[i]) << 4);
                ldm4(af[i], ad + OFF_A);
            }
            #pragma unroll
            for (int p = 0; p < 2; p++) {
                uint32_t bd = base + bRow[p] + ((bc ^ bSw[p]) << 4);
                ldm4(bh[p], bd + OFF_BH);
                ldm4(bl[p], bd + OFF_BL);
            }
            #pragma unroll
            for (int i = 0; i < 4; i++)
                #pragma unroll
                for (int j = 0; j < 4; j++) {
                    const int p = j >> 1, q = (j & 1) * 2;
                    mma16816(acc[i][j], af[i], bh[p][q], bh[p][q + 1]);
                    mma16816(acc[i][j], af[i], bl[p][q], bl[p][q + 1]);
                }
        }
    }

    // ---- epilogue
    const int gID = lane >> 2, tig = lane & 3;
    float cl[4][2], ul[4][2];
    #pragma unroll
    for (int j = 0; j < 4; j++) {
        const int ag = a0 + warp_n * 32 + j * 8 + 2 * tig;
        cl[j][0] = g_c[ag];  cl[j][1] = g_c[ag + 1];
        ul[j][0] = u_in[ag]; ul[j][1] = u_in[ag + 1];
    }
    #pragma unroll
    for (int i = 0; i < 4; i++) {
        float sA = 0.0f, sB = 0.0f;
        #pragma unroll
        for (int j = 0; j < 4; j++) {
            sA = fmaf(tanh_fast(acc[i][j][0] + cl[j][0]), ul[j][0], sA);
            sA = fmaf(tanh_fast(acc[i][j][1] + cl[j][1]), ul[j][1], sA);
            sB = fmaf(tanh_fast(acc[i][j][2] + cl[j][0]), ul[j][0], sB);
            sB = fmaf(tanh_fast(acc[i][j][3] + cl[j][1]), ul[j][1], sB);
        }
        sA += __shfl_xor_sync(0xffffffffu, sA, 1);
        sA += __shfl_xor_sync(0xffffffffu, sA, 2);
        sB += __shfl_xor_sync(0xffffffffu, sB, 1);
        sB += __shfl_xor_sync(0xffffffffu, sB, 2);
        if (tig == 0) {
            const int r = l0 + warp_m * 64 + i * 16 + gID;
            atomicAdd(&g_beta[r], sA);
            atomicAdd(&g_beta[r + 8], sB);
        }
    }
}

// ---------------------------------------------------------------------------
// K4: global max of beta
// ---------------------------------------------------------------------------
__global__ void k_max() {
    int i = blockIdx.x * 1024 + threadIdx.x;
    float v = g_beta[i];
    #pragma unroll
    for (int o = 16; o > 0; o >>= 1) v = fmaxf(v, __shfl_xor_sync(0xffffffffu, v, o));
    __shared__ float r[32];
    if ((threadIdx.x & 31) == 0) r[threadIdx.x >> 5] = v;
    __syncthreads();
    if (threadIdx.x < 32) {
        v = r[threadIdx.x];
        #pragma unroll
        for (int o = 16; o > 0; o >>= 1) v = fmaxf(v, __shfl_xor_sync(0xffffffffu, v, o));
        if (threadIdx.x == 0) atomicMax(&g_maxbits, enc_f(v));
    }
}

// ---------------------------------------------------------------------------
// K5: unnormalized s[d] += sum_l exp(beta_l - max) * hA[l][d]  (fp16 source)
//   thread owns 4 consecutive cols (8B coalesced loads), rows unrolled x2
// ---------------------------------------------------------------------------
#define OROWS 128
__global__ void __launch_bounds__(256) k_out(float* __restrict__ out) {
    __shared__ float w[OROWS];
    int l0 = blockIdx.x * OROWS;
    int tid = threadIdx.x;
    float mx = dec_f(g_maxbits);
    if (tid < OROWS) w[tid] = expf(g_beta[l0 + tid] - mx);
    __syncthreads();
    if (tid < 32) {
        float s = 0.0f;
        #pragma unroll
        for (int k = 0; k < OROWS / 32; k++) s += w[tid + k * 32];
        #pragma unroll
        for (int o = 16; o > 0; o >>= 1) s += __shfl_xor_sync(0xffffffffu, s, o);
        if (tid == 0) atomicAdd(&g_sumexp, s);
    }
    const __half* base = g_A + (size_t)l0 * D + tid * 4;
    float acc0 = 0.0f, acc1 = 0.0f, acc2 = 0.0f, acc3 = 0.0f;
    #pragma unroll 1
    for (int l = 0; l < OROWS; l += 2) {
        float w0 = w[l], w1 = w[l + 1];
        uint2 v0 = *(const uint2*)(base + (size_t)l * D);
        uint2 v1 = *(const uint2*)(base + (size_t)(l + 1) * D);
        float2 a0 = __half22float2(*(const __half2*)&v0.x);
        float2 b0 = __half22float2(*(const __half2*)&v0.y);
        float2 a1 = __half22float2(*(const __half2*)&v1.x);
        float2 b1 = __half22float2(*(const __half2*)&v1.y);
        acc0 = fmaf(w1, a1.x, fmaf(w0, a0.x, acc0));
        acc1 = fmaf(w1, a1.y, fmaf(w0, a0.y, acc1));
        acc2 = fmaf(w1, b1.x, fmaf(w0, b0.x, acc2));
        acc3 = fmaf(w1, b1.y, fmaf(w0, b0.y, acc3));
    }
    atomicAdd(&out[tid * 4 + 0], acc0);
    atomicAdd(&out[tid * 4 + 1], acc1);
    atomicAdd(&out[tid * 4 + 2], acc2);
    atomicAdd(&out[tid * 4 + 3], acc3);
}

// ---------------------------------------------------------------------------
// K6: normalize out by 1/sumexp
// ---------------------------------------------------------------------------
__global__ void k_norm(float* __restrict__ out) {
    float inv = __frcp_rn(g_sumexp);
    out[blockIdx.x * 256 + threadIdx.x] *= inv;
}

// ---------------------------------------------------------------------------
extern "C" void kernel_launch(void* const* d_in, const int* in_sizes, int n_in,
                              void* d_out, int out_size) {
    const float* h_i = (const float*)d_in[0];
    const float* h_t = (const float*)d_in[1];
    const float* W   = (const float*)d_in[2];
    const float* b   = (const float*)d_in[3];
    const float* u   = (const float*)d_in[4];
    float* out = (float*)d_out;

    static bool attr_set = false;
    if (!attr_set) {
        cudaFuncSetAttribute(k_gemm, cudaFuncAttributeMaxDynamicSharedMemorySize, SMEM_TOTAL);
        attr_set = true;
    }

    k_ctx<<<ADIM, 256>>>(W, h_t, b, out);
    k_conv<<<HBLK + WBLK, 256>>>(h_i, W);
    dim3 g(ADIM / BN, L / BM);
    k_gemm<<<g, 256, SMEM_TOTAL>>>(u);   // 3rd launch now; ncu window still covers it (-s 5 -c 1 on graph replays)
    k_max<<<16, 1024>>>();
    k_out<<<L / OROWS, 256>>>(out);
    k_norm<<<4, 256>>>(out);
}